// round 2
// baseline (speedup 1.0000x reference)
#include <cuda_runtime.h>
#include <cuda_bf16.h>
#include <cstdint>

#define N_NODES 50000
#define N_EDGES 600000
#define EMB_D   128
#define NUM_LAYER 5
#define BN_EPS  1e-5f

// ---------------- scratch (static device globals; no allocation) ----------------
__device__ float g_h[(size_t)N_NODES * EMB_D];            // node features (post-BN/ReLU)
__device__ float g_agg[(size_t)N_NODES * EMB_D];          // scatter accumulator, reused as h2
__device__ float g_t[(size_t)N_NODES * 2 * EMB_D];        // hidden 2d activations
__device__ float g_stats[2 * EMB_D];                      // [0:128) sum, [128:256) sumsq

// ---------------- kernels ----------------

// h0[n,:] = atom_emb[x0] + chir_emb[x1] + hyb_emb[x2], one thread per float4
__global__ void embed_kernel(const int* __restrict__ x,
                             const float* __restrict__ atom,
                             const float* __restrict__ chir,
                             const float* __restrict__ hyb,
                             float* __restrict__ h)
{
    int i = blockIdx.x * blockDim.x + threadIdx.x;      // over N*D/4
    const int V = EMB_D / 4;
    if (i >= N_NODES * V) return;
    int node = i / V;
    int c4 = (i - node * V) * 4;
    int x0 = x[node * 3 + 0];
    int x1 = x[node * 3 + 1];
    int x2 = x[node * 3 + 2];
    float4 a = *reinterpret_cast<const float4*>(&atom[(size_t)x0 * EMB_D + c4]);
    float4 b = *reinterpret_cast<const float4*>(&chir[(size_t)x1 * EMB_D + c4]);
    float4 c = *reinterpret_cast<const float4*>(&hyb [(size_t)x2 * EMB_D + c4]);
    float4 o;
    o.x = a.x + b.x + c.x; o.y = a.y + b.y + c.y;
    o.z = a.z + b.z + c.z; o.w = a.w + b.w + c.w;
    *reinterpret_cast<float4*>(&h[(size_t)node * EMB_D + c4]) = o;
}

// one warp per edge: msg = h[src] + e1[attr0] + e2[attr1]; vector-red into agg[dst]
__global__ void scatter_kernel(const float* __restrict__ h,
                               const int* __restrict__ ei,     // [2, E]
                               const int* __restrict__ ea,     // [E, 2]
                               const float* __restrict__ e1l,  // [6, D]
                               const float* __restrict__ e2l,  // [4, D]
                               float* __restrict__ agg)
{
    int gw = (blockIdx.x * blockDim.x + threadIdx.x) >> 5;
    int lane = threadIdx.x & 31;
    if (gw >= N_EDGES) return;
    int src = ei[gw];
    int dst = ei[N_EDGES + gw];
    int a0 = ea[2 * gw];
    int a1 = ea[2 * gw + 1];
    int c4 = lane * 4;
    float4 hv = *reinterpret_cast<const float4*>(&h  [(size_t)src * EMB_D + c4]);
    float4 v1 = *reinterpret_cast<const float4*>(&e1l[(size_t)a0  * EMB_D + c4]);
    float4 v2 = *reinterpret_cast<const float4*>(&e2l[(size_t)a1  * EMB_D + c4]);
    float4 m;
    m.x = hv.x + v1.x + v2.x;
    m.y = hv.y + v1.y + v2.y;
    m.z = hv.z + v1.z + v2.z;
    m.w = hv.w + v1.w + v2.w;
    float* p = &agg[(size_t)dst * EMB_D + c4];
    asm volatile("red.global.add.v4.f32 [%0], {%1,%2,%3,%4};"
                 :: "l"(p), "f"(m.x), "f"(m.y), "f"(m.z), "f"(m.w)
                 : "memory");
}

// C[M,N] = A[M,K] @ B[K,N] + bias, optional ReLU. 64x64 tile, 256 threads, 4x4/thread.
// N and K must be multiples of 64/16 (they are: N in {256,128}, K in {128,256}).
__global__ __launch_bounds__(256)
void sgemm_bias(const float* __restrict__ A, const float* __restrict__ B,
                const float* __restrict__ bias, float* __restrict__ C,
                int M, int K, int N, int relu)
{
    const int BM = 64, BN = 64, BK = 16;
    __shared__ float As[BK][BM];
    __shared__ float Bs[BK][BN];

    int tid = threadIdx.x;
    int tx = tid & 15;        // 0..15 -> col group
    int ty = tid >> 4;        // 0..15 -> row group
    int rowBase = blockIdx.y * BM;
    int colBase = blockIdx.x * BN;

    // A tile load mapping: 64 rows x 16 cols, one float4 per thread
    int arow = tid >> 2;           // 0..63
    int acol = (tid & 3) * 4;      // 0,4,8,12
    // B tile load mapping: 16 rows x 64 cols, one float4 per thread
    int brow = tid >> 4;           // 0..15
    int bcol = (tid & 15) * 4;     // 0..60

    float acc[4][4];
    #pragma unroll
    for (int i = 0; i < 4; i++)
        #pragma unroll
        for (int j = 0; j < 4; j++) acc[i][j] = 0.f;

    for (int k0 = 0; k0 < K; k0 += BK) {
        int gr = rowBase + arow;
        float4 av = make_float4(0.f, 0.f, 0.f, 0.f);
        if (gr < M)
            av = *reinterpret_cast<const float4*>(&A[(size_t)gr * K + k0 + acol]);
        As[acol + 0][arow] = av.x;
        As[acol + 1][arow] = av.y;
        As[acol + 2][arow] = av.z;
        As[acol + 3][arow] = av.w;

        *reinterpret_cast<float4*>(&Bs[brow][bcol]) =
            *reinterpret_cast<const float4*>(&B[(size_t)(k0 + brow) * N + colBase + bcol]);
        __syncthreads();

        #pragma unroll
        for (int k = 0; k < BK; k++) {
            float4 am = *reinterpret_cast<const float4*>(&As[k][ty * 4]);
            float4 bn = *reinterpret_cast<const float4*>(&Bs[k][tx * 4]);
            acc[0][0] += am.x * bn.x; acc[0][1] += am.x * bn.y;
            acc[0][2] += am.x * bn.z; acc[0][3] += am.x * bn.w;
            acc[1][0] += am.y * bn.x; acc[1][1] += am.y * bn.y;
            acc[1][2] += am.y * bn.z; acc[1][3] += am.y * bn.w;
            acc[2][0] += am.z * bn.x; acc[2][1] += am.z * bn.y;
            acc[2][2] += am.z * bn.z; acc[2][3] += am.z * bn.w;
            acc[3][0] += am.w * bn.x; acc[3][1] += am.w * bn.y;
            acc[3][2] += am.w * bn.z; acc[3][3] += am.w * bn.w;
        }
        __syncthreads();
    }

    #pragma unroll
    for (int i = 0; i < 4; i++) {
        int r = rowBase + ty * 4 + i;
        if (r >= M) continue;
        #pragma unroll
        for (int j = 0; j < 4; j++) {
            int c = colBase + tx * 4 + j;
            float v = acc[i][j] + bias[c];
            if (relu) v = fmaxf(v, 0.f);
            C[(size_t)r * N + c] = v;
        }
    }
}

// per-column sum / sumsq partials (blockDim.x == 128 == EMB_D)
__global__ void bn_stats_kernel(const float* __restrict__ h2, float* __restrict__ stats,
                                int rowsPerBlock)
{
    int c = threadIdx.x;
    int r0 = blockIdx.x * rowsPerBlock;
    int r1 = r0 + rowsPerBlock;
    if (r1 > N_NODES) r1 = N_NODES;
    float s = 0.f, ss = 0.f;
    for (int r = r0; r < r1; r++) {
        float v = h2[(size_t)r * EMB_D + c];
        s += v;
        ss += v * v;
    }
    atomicAdd(&stats[c], s);
    atomicAdd(&stats[EMB_D + c], ss);
}

// out = gamma*(h2-mu)*rsqrt(var+eps)+beta, optional ReLU
__global__ void bn_apply_kernel(const float* __restrict__ h2,
                                const float* __restrict__ stats,
                                const float* __restrict__ gamma,
                                const float* __restrict__ beta,
                                float* __restrict__ out, int relu)
{
    int i = blockIdx.x * blockDim.x + threadIdx.x;
    if (i >= N_NODES * EMB_D) return;
    int c = i & (EMB_D - 1);
    const float invN = 1.0f / (float)N_NODES;
    float mu = stats[c] * invN;
    float var = stats[EMB_D + c] * invN - mu * mu;
    float v = gamma[c] * (h2[i] - mu) * rsqrtf(var + BN_EPS) + beta[c];
    if (relu) v = fmaxf(v, 0.f);
    out[i] = v;
}

// ---------------- launch ----------------
extern "C" void kernel_launch(void* const* d_in, const int* in_sizes, int n_in,
                              void* d_out, int out_size)
{
    const int*   x    = (const int*)  d_in[0];
    const int*   ei   = (const int*)  d_in[1];
    const int*   ea   = (const int*)  d_in[2];
    const float* atom = (const float*)d_in[3];
    const float* chir = (const float*)d_in[4];
    const float* hyb  = (const float*)d_in[5];
    const float* e1   = (const float*)d_in[6];   // [L,6,D]
    const float* e2   = (const float*)d_in[7];   // [L,4,D]
    const float* W1   = (const float*)d_in[8];   // [L,D,2D]
    const float* b1   = (const float*)d_in[9];   // [L,2D]
    const float* W2   = (const float*)d_in[10];  // [L,2D,D]
    const float* b2   = (const float*)d_in[11];  // [L,D]
    const float* gam  = (const float*)d_in[12];  // [L,D]
    const float* bet  = (const float*)d_in[13];  // [L,D]
    float* out = (float*)d_out;

    float *p_h, *p_agg, *p_t, *p_stats;
    cudaGetSymbolAddress((void**)&p_h, g_h);
    cudaGetSymbolAddress((void**)&p_agg, g_agg);
    cudaGetSymbolAddress((void**)&p_t, g_t);
    cudaGetSymbolAddress((void**)&p_stats, g_stats);

    // input node embedding
    {
        int total = N_NODES * (EMB_D / 4);
        embed_kernel<<<(total + 255) / 256, 256>>>(x, atom, chir, hyb, p_h);
    }

    const int scatterBlocks = (N_EDGES * 32 + 255) / 256;
    const int rowsPerBlock = 256;
    const int statBlocks = (N_NODES + rowsPerBlock - 1) / rowsPerBlock;
    const int ewTotal = N_NODES * EMB_D;

    for (int l = 0; l < NUM_LAYER; l++) {
        // zero accumulator + stats
        cudaMemsetAsync(p_agg, 0, (size_t)N_NODES * EMB_D * sizeof(float));
        cudaMemsetAsync(p_stats, 0, 2 * EMB_D * sizeof(float));

        // message passing: agg[dst] += h[src] + e1[attr0] + e2[attr1]
        scatter_kernel<<<scatterBlocks, 256>>>(
            p_h, ei, ea,
            e1 + (size_t)l * 6 * EMB_D,
            e2 + (size_t)l * 4 * EMB_D,
            p_agg);

        // MLP: t = relu(agg @ W1 + b1)   [N, 2D]
        {
            dim3 grid((2 * EMB_D) / 64, (N_NODES + 63) / 64);
            sgemm_bias<<<grid, 256>>>(p_agg,
                                      W1 + (size_t)l * EMB_D * 2 * EMB_D,
                                      b1 + (size_t)l * 2 * EMB_D,
                                      p_t, N_NODES, EMB_D, 2 * EMB_D, 1);
        }
        // h2 = t @ W2 + b2   [N, D]  (reuse agg buffer — agg fully consumed)
        {
            dim3 grid(EMB_D / 64, (N_NODES + 63) / 64);
            sgemm_bias<<<grid, 256>>>(p_t,
                                      W2 + (size_t)l * 2 * EMB_D * EMB_D,
                                      b2 + (size_t)l * EMB_D,
                                      p_agg, N_NODES, 2 * EMB_D, EMB_D, 0);
        }

        // batch-norm statistics
        bn_stats_kernel<<<statBlocks, EMB_D>>>(p_agg, p_stats, rowsPerBlock);

        // normalize (+ReLU except last layer); last layer writes d_out
        float* dst = (l == NUM_LAYER - 1) ? out : p_h;
        int relu = (l == NUM_LAYER - 1) ? 0 : 1;
        bn_apply_kernel<<<(ewTotal + 255) / 256, 256>>>(
            p_agg, p_stats, gam + (size_t)l * EMB_D, bet + (size_t)l * EMB_D,
            dst, relu);
    }
}

// round 7
// speedup vs baseline: 1.6807x; 1.6807x over previous
#include <cuda_runtime.h>
#include <cuda_bf16.h>
#include <cstdint>

#define N_NODES 50000
#define N_EDGES 600000
#define EMB_D   128
#define NUM_LAYER 5
#define BN_EPS  1e-5f

// ---------------- scratch (static device globals; no allocation) ----------------
__device__ float g_h[(size_t)N_NODES * EMB_D];
__device__ float g_agg[(size_t)N_NODES * EMB_D];
__device__ float g_t[(size_t)N_NODES * 2 * EMB_D];
__device__ float g_stats[2 * EMB_D];

// ---------------- kernels ----------------

__global__ void embed_kernel(const int* __restrict__ x,
                             const float* __restrict__ atom,
                             const float* __restrict__ chir,
                             const float* __restrict__ hyb,
                             float* __restrict__ h)
{
    int i = blockIdx.x * blockDim.x + threadIdx.x;
    const int V = EMB_D / 4;
    if (i >= N_NODES * V) return;
    int node = i / V;
    int c4 = (i - node * V) * 4;
    int x0 = x[node * 3 + 0];
    int x1 = x[node * 3 + 1];
    int x2 = x[node * 3 + 2];
    float4 a = *reinterpret_cast<const float4*>(&atom[(size_t)x0 * EMB_D + c4]);
    float4 b = *reinterpret_cast<const float4*>(&chir[(size_t)x1 * EMB_D + c4]);
    float4 c = *reinterpret_cast<const float4*>(&hyb [(size_t)x2 * EMB_D + c4]);
    float4 o;
    o.x = a.x + b.x + c.x; o.y = a.y + b.y + c.y;
    o.z = a.z + b.z + c.z; o.w = a.w + b.w + c.w;
    *reinterpret_cast<float4*>(&h[(size_t)node * EMB_D + c4]) = o;
}

// one warp per edge: msg = h[src] + e1[attr0] + e2[attr1]; vector-red into agg[dst]
__global__ void scatter_kernel(const float* __restrict__ h,
                               const int* __restrict__ ei,
                               const int* __restrict__ ea,
                               const float* __restrict__ e1l,
                               const float* __restrict__ e2l,
                               float* __restrict__ agg)
{
    int gw = (blockIdx.x * blockDim.x + threadIdx.x) >> 5;
    int lane = threadIdx.x & 31;
    if (gw >= N_EDGES) return;
    int src = ei[gw];
    int dst = ei[N_EDGES + gw];
    int a0 = ea[2 * gw];
    int a1 = ea[2 * gw + 1];
    int c4 = lane * 4;
    float4 hv = *reinterpret_cast<const float4*>(&h  [(size_t)src * EMB_D + c4]);
    float4 v1 = *reinterpret_cast<const float4*>(&e1l[(size_t)a0  * EMB_D + c4]);
    float4 v2 = *reinterpret_cast<const float4*>(&e2l[(size_t)a1  * EMB_D + c4]);
    float4 m;
    m.x = hv.x + v1.x + v2.x;
    m.y = hv.y + v1.y + v2.y;
    m.z = hv.z + v1.z + v2.z;
    m.w = hv.w + v1.w + v2.w;
    float* p = &agg[(size_t)dst * EMB_D + c4];
    asm volatile("red.global.add.v4.f32 [%0], {%1,%2,%3,%4};"
                 :: "l"(p), "f"(m.x), "f"(m.y), "f"(m.z), "f"(m.w)
                 : "memory");
}

// --------- high-intensity SGEMM: BMxBN tile, 256 threads, TMxTN microtile,
// double-buffered smem, fused bias (+ReLU) and optional fused BN-stats epilogue.
template<int BM, int BN, int BK, int TM, int TN, int DO_RELU, int FUSE_STATS>
__global__ __launch_bounds__(256, 2)
void sgemm_k(const float* __restrict__ A, const float* __restrict__ B,
             const float* __restrict__ bias, float* __restrict__ C,
             int M, int K, int N, float* __restrict__ stats)
{
    constexpr int THREADS = 256;
    constexpr int NX = BN / TN;           // threads along N
    constexpr int NY = BM / TM;           // threads along M
    static_assert(NX * NY == THREADS, "thread tiling");
    constexpr int A4 = BM * BK / 4 / THREADS;
    constexpr int B4 = BK * BN / 4 / THREADS;
    constexpr int CHUNKS = TN / 4;        // split-B fragment chunks
    constexpr int STRIDE = BN / CHUNKS;

    __shared__ float As[2][BK][BM + 4];
    __shared__ float Bs[2][BK][BN];

    int tid = threadIdx.x;
    int tx = tid % NX;
    int ty = tid / NX;
    int rowBase = blockIdx.y * BM;
    int colBase = blockIdx.x * BN;

    float acc[TM][TN];
    #pragma unroll
    for (int i = 0; i < TM; i++)
        #pragma unroll
        for (int j = 0; j < TN; j++) acc[i][j] = 0.f;

    float4 stA[A4], stB[B4];

    // ---- tile 0 -> smem[0] ----
    #pragma unroll
    for (int i = 0; i < A4; i++) {
        int idx = tid + i * THREADS;
        int ar = idx / (BK / 4), ac = (idx % (BK / 4)) * 4;
        int gr = rowBase + ar;
        float4 v = make_float4(0.f, 0.f, 0.f, 0.f);
        if (gr < M) v = *reinterpret_cast<const float4*>(&A[(size_t)gr * K + ac]);
        As[0][ac + 0][ar] = v.x; As[0][ac + 1][ar] = v.y;
        As[0][ac + 2][ar] = v.z; As[0][ac + 3][ar] = v.w;
    }
    #pragma unroll
    for (int i = 0; i < B4; i++) {
        int idx = tid + i * THREADS;
        int br = idx / (BN / 4), bc = (idx % (BN / 4)) * 4;
        *reinterpret_cast<float4*>(&Bs[0][br][bc]) =
            *reinterpret_cast<const float4*>(&B[(size_t)br * N + colBase + bc]);
    }
    __syncthreads();

    int KT = K / BK;
    int cur = 0;
    for (int kt = 0; kt < KT; kt++) {
        if (kt + 1 < KT) {
            int k0 = (kt + 1) * BK;
            #pragma unroll
            for (int i = 0; i < A4; i++) {
                int idx = tid + i * THREADS;
                int ar = idx / (BK / 4), ac = (idx % (BK / 4)) * 4;
                int gr = rowBase + ar;
                stA[i] = (gr < M)
                    ? *reinterpret_cast<const float4*>(&A[(size_t)gr * K + k0 + ac])
                    : make_float4(0.f, 0.f, 0.f, 0.f);
            }
            #pragma unroll
            for (int i = 0; i < B4; i++) {
                int idx = tid + i * THREADS;
                int br = idx / (BN / 4), bc = (idx % (BN / 4)) * 4;
                stB[i] = *reinterpret_cast<const float4*>(&B[(size_t)(k0 + br) * N + colBase + bc]);
            }
        }
        #pragma unroll
        for (int k = 0; k < BK; k++) {
            float af[TM], bf[TN];
            #pragma unroll
            for (int i = 0; i < TM; i += 4)
                *reinterpret_cast<float4*>(&af[i]) =
                    *reinterpret_cast<const float4*>(&As[cur][k][ty * TM + i]);
            #pragma unroll
            for (int c = 0; c < CHUNKS; c++)
                *reinterpret_cast<float4*>(&bf[c * 4]) =
                    *reinterpret_cast<const float4*>(&Bs[cur][k][c * STRIDE + tx * 4]);
            #pragma unroll
            for (int i = 0; i < TM; i++)
                #pragma unroll
                for (int j = 0; j < TN; j++)
                    acc[i][j] += af[i] * bf[j];
        }
        if (kt + 1 < KT) {
            int nb = cur ^ 1;
            #pragma unroll
            for (int i = 0; i < A4; i++) {
                int idx = tid + i * THREADS;
                int ar = idx / (BK / 4), ac = (idx % (BK / 4)) * 4;
                As[nb][ac + 0][ar] = stA[i].x; As[nb][ac + 1][ar] = stA[i].y;
                As[nb][ac + 2][ar] = stA[i].z; As[nb][ac + 3][ar] = stA[i].w;
            }
            #pragma unroll
            for (int i = 0; i < B4; i++) {
                int idx = tid + i * THREADS;
                int br = idx / (BN / 4), bc = (idx % (BN / 4)) * 4;
                *reinterpret_cast<float4*>(&Bs[nb][br][bc]) = stB[i];
            }
            __syncthreads();
            cur = nb;
        }
    }

    // ---- epilogue: bias (+ReLU), store, optional fused BN stats ----
    float colS[TN], colSS[TN];
    #pragma unroll
    for (int j = 0; j < TN; j++) { colS[j] = 0.f; colSS[j] = 0.f; }

    #pragma unroll
    for (int i = 0; i < TM; i++) {
        int r = rowBase + ty * TM + i;
        if (r < M) {
            #pragma unroll
            for (int j = 0; j < TN; j++) {
                int cloc = (j / 4) * STRIDE + tx * 4 + (j & 3);
                int c = colBase + cloc;
                float v = acc[i][j] + bias[c];
                if (DO_RELU) v = fmaxf(v, 0.f);
                C[(size_t)r * N + c] = v;
                if (FUSE_STATS) { colS[j] += v; colSS[j] += v * v; }
            }
        }
    }

    if (FUSE_STATS) {
        // reuse As as [NY][BN] partial sum + [NY][BN] partial sumsq
        __syncthreads();   // everyone done reading As
        float* psum = reinterpret_cast<float*>(As);
        float* psq  = psum + NY * BN;
        static_assert(2 * NY * BN <= 2 * BK * (BM + 4), "stats smem fits in As");
        #pragma unroll
        for (int j = 0; j < TN; j++) {
            int cloc = (j / 4) * STRIDE + tx * 4 + (j & 3);
            psum[ty * BN + cloc] = colS[j];
            psq [ty * BN + cloc] = colSS[j];
        }
        __syncthreads();
        if (tid < 2 * BN) {
            int c = tid % BN;
            bool sq = tid >= BN;
            const float* base = sq ? psq : psum;
            float s = 0.f;
            #pragma unroll
            for (int y = 0; y < NY; y++) s += base[y * BN + c];
            atomicAdd(&stats[(sq ? EMB_D : 0) + colBase + c], s);
        }
    }
}

// out = gamma*(h2-mu)*rsqrt(var+eps)+beta, optional ReLU
__global__ void bn_apply_kernel(const float* __restrict__ h2,
                                const float* __restrict__ stats,
                                const float* __restrict__ gamma,
                                const float* __restrict__ beta,
                                float* __restrict__ out, int relu)
{
    int i = blockIdx.x * blockDim.x + threadIdx.x;
    if (i >= N_NODES * EMB_D) return;
    int c = i & (EMB_D - 1);
    const float invN = 1.0f / (float)N_NODES;
    float mu = stats[c] * invN;
    float var = stats[EMB_D + c] * invN - mu * mu;
    float v = gamma[c] * (h2[i] - mu) * rsqrtf(var + BN_EPS) + beta[c];
    if (relu) v = fmaxf(v, 0.f);
    out[i] = v;
}

// ---------------- launch ----------------
extern "C" void kernel_launch(void* const* d_in, const int* in_sizes, int n_in,
                              void* d_out, int out_size)
{
    const int*   x    = (const int*)  d_in[0];
    const int*   ei   = (const int*)  d_in[1];
    const int*   ea   = (const int*)  d_in[2];
    const float* atom = (const float*)d_in[3];
    const float* chir = (const float*)d_in[4];
    const float* hyb  = (const float*)d_in[5];
    const float* e1   = (const float*)d_in[6];
    const float* e2   = (const float*)d_in[7];
    const float* W1   = (const float*)d_in[8];
    const float* b1   = (const float*)d_in[9];
    const float* W2   = (const float*)d_in[10];
    const float* b2   = (const float*)d_in[11];
    const float* gam  = (const float*)d_in[12];
    const float* bet  = (const float*)d_in[13];
    float* out = (float*)d_out;

    float *p_h, *p_agg, *p_t, *p_stats;
    cudaGetSymbolAddress((void**)&p_h, g_h);
    cudaGetSymbolAddress((void**)&p_agg, g_agg);
    cudaGetSymbolAddress((void**)&p_t, g_t);
    cudaGetSymbolAddress((void**)&p_stats, g_stats);

    {
        int total = N_NODES * (EMB_D / 4);
        embed_kernel<<<(total + 255) / 256, 256>>>(x, atom, chir, hyb, p_h);
    }

    const int scatterBlocks = (N_EDGES * 32 + 255) / 256;
    const int ewTotal = N_NODES * EMB_D;

    for (int l = 0; l < NUM_LAYER; l++) {
        cudaMemsetAsync(p_agg, 0, (size_t)N_NODES * EMB_D * sizeof(float));
        cudaMemsetAsync(p_stats, 0, 2 * EMB_D * sizeof(float));

        scatter_kernel<<<scatterBlocks, 256>>>(
            p_h, ei, ea,
            e1 + (size_t)l * 6 * EMB_D,
            e2 + (size_t)l * 4 * EMB_D,
            p_agg);

        // GEMM1: t = relu(agg @ W1 + b1)   [N, 256]  (128x128 tile, 8x8)
        {
            dim3 grid((2 * EMB_D) / 128, (N_NODES + 127) / 128);
            sgemm_k<128, 128, 16, 8, 8, 1, 0><<<grid, 256>>>(
                p_agg, W1 + (size_t)l * EMB_D * 2 * EMB_D,
                b1 + (size_t)l * 2 * EMB_D, p_t,
                N_NODES, EMB_D, 2 * EMB_D, nullptr);
        }
        // GEMM2: h2 = t @ W2 + b2  [N, 128], fused BN stats (128x64 tile, 8x4)
        {
            dim3 grid(EMB_D / 64, (N_NODES + 127) / 128);
            sgemm_k<128, 64, 16, 8, 4, 0, 1><<<grid, 256>>>(
                p_t, W2 + (size_t)l * 2 * EMB_D * EMB_D,
                b2 + (size_t)l * EMB_D, p_agg,
                N_NODES, 2 * EMB_D, EMB_D, p_stats);
        }

        float* dst = (l == NUM_LAYER - 1) ? out : p_h;
        int relu = (l == NUM_LAYER - 1) ? 0 : 1;
        bn_apply_kernel<<<(ewTotal + 255) / 256, 256>>>(
            p_agg, p_stats, gam + (size_t)l * EMB_D, bet + (size_t)l * EMB_D,
            dst, relu);
    }
}

// round 13
// speedup vs baseline: 1.7739x; 1.0554x over previous
#include <cuda_runtime.h>
#include <cuda_bf16.h>
#include <cstdint>

#define N_NODES 50000
#define N_EDGES 600000
#define EMB_D   128
#define NUM_LAYER 5
#define BN_EPS  1e-5f

// ---------------- scratch (static device globals; no allocation) ----------------
__device__ float g_h[(size_t)N_NODES * EMB_D];
__device__ float g_agg[(size_t)N_NODES * EMB_D];
__device__ float g_t[(size_t)N_NODES * 2 * EMB_D];
__device__ float g_stats[2 * EMB_D];

// ---------------- small helpers ----------------
__device__ __forceinline__ float tf32r(float x) {
    float y;
    asm("cvt.rna.tf32.f32 %0, %1;" : "=f"(y) : "f"(x));
    return y;
}

__device__ __forceinline__ uint32_t smemU32(const void* p) {
    uint32_t a;
    asm("{ .reg .u64 t; cvta.to.shared.u64 t, %1; cvt.u32.u64 %0, t; }"
        : "=r"(a) : "l"(p));
    return a;
}

__device__ __forceinline__ void ldsm4(uint32_t* r, uint32_t addr) {
    asm volatile("ldmatrix.sync.aligned.m8n8.x4.shared.b16 {%0,%1,%2,%3}, [%4];"
                 : "=r"(r[0]), "=r"(r[1]), "=r"(r[2]), "=r"(r[3]) : "r"(addr));
}

__device__ __forceinline__ void mma_tf32(float* d, const uint32_t* a, const uint32_t* b) {
    asm volatile("mma.sync.aligned.m16n8k8.row.col.f32.tf32.tf32.f32 "
                 "{%0,%1,%2,%3}, {%4,%5,%6,%7}, {%8,%9}, {%0,%1,%2,%3};"
                 : "+f"(d[0]), "+f"(d[1]), "+f"(d[2]), "+f"(d[3])
                 : "r"(a[0]), "r"(a[1]), "r"(a[2]), "r"(a[3]),
                   "r"(b[0]), "r"(b[1]));
}

// ---------------- kernels ----------------

__global__ void embed_kernel(const int* __restrict__ x,
                             const float* __restrict__ atom,
                             const float* __restrict__ chir,
                             const float* __restrict__ hyb,
                             float* __restrict__ h)
{
    int i = blockIdx.x * blockDim.x + threadIdx.x;
    const int V = EMB_D / 4;
    if (i >= N_NODES * V) return;
    int node = i / V;
    int c4 = (i - node * V) * 4;
    int x0 = x[node * 3 + 0];
    int x1 = x[node * 3 + 1];
    int x2 = x[node * 3 + 2];
    float4 a = *reinterpret_cast<const float4*>(&atom[(size_t)x0 * EMB_D + c4]);
    float4 b = *reinterpret_cast<const float4*>(&chir[(size_t)x1 * EMB_D + c4]);
    float4 c = *reinterpret_cast<const float4*>(&hyb [(size_t)x2 * EMB_D + c4]);
    float4 o;
    o.x = a.x + b.x + c.x; o.y = a.y + b.y + c.y;
    o.z = a.z + b.z + c.z; o.w = a.w + b.w + c.w;
    *reinterpret_cast<float4*>(&h[(size_t)node * EMB_D + c4]) = o;
}

// one warp per edge: msg = h[src] + e1[attr0] + e2[attr1]; vector-red into agg[dst]
__global__ void scatter_kernel(const float* __restrict__ h,
                               const int* __restrict__ ei,
                               const int* __restrict__ ea,
                               const float* __restrict__ e1l,
                               const float* __restrict__ e2l,
                               float* __restrict__ agg)
{
    int gw = (blockIdx.x * blockDim.x + threadIdx.x) >> 5;
    int lane = threadIdx.x & 31;
    if (gw >= N_EDGES) return;
    int src = ei[gw];
    int dst = ei[N_EDGES + gw];
    int a0 = ea[2 * gw];
    int a1 = ea[2 * gw + 1];
    int c4 = lane * 4;
    float4 hv = *reinterpret_cast<const float4*>(&h  [(size_t)src * EMB_D + c4]);
    float4 v1 = *reinterpret_cast<const float4*>(&e1l[(size_t)a0  * EMB_D + c4]);
    float4 v2 = *reinterpret_cast<const float4*>(&e2l[(size_t)a1  * EMB_D + c4]);
    float4 m;
    m.x = hv.x + v1.x + v2.x;
    m.y = hv.y + v1.y + v2.y;
    m.z = hv.z + v1.z + v2.z;
    m.w = hv.w + v1.w + v2.w;
    float* p = &agg[(size_t)dst * EMB_D + c4];
    asm volatile("red.global.add.v4.f32 [%0], {%1,%2,%3,%4};"
                 :: "l"(p), "f"(m.x), "f"(m.y), "f"(m.z), "f"(m.w)
                 : "memory");
}

// ------- 3xTF32 tensor-core GEMM: C[M,N] = A[M,K] @ B[K,N] + bias, fp32-accurate.
// Split each operand x = hi + lo (both tf32); acc += hi*hi + hi*lo + lo*hi.
// CTA 128x128, 512 threads = 16 warps (4m x 4n), warp tile 32x32, BK=8,
// double-buffered smem, fused bias(+ReLU) and optional fused BN-stats epilogue.
template<int DO_RELU, int FUSE_STATS>
__global__ __launch_bounds__(512, 1)
void tmma_gemm(const float* __restrict__ A, const float* __restrict__ B,
               const float* __restrict__ bias, float* __restrict__ C,
               int M, int K, int N, float* __restrict__ stats)
{
    constexpr int BM = 128, BN = 128, BK = 8;
    constexpr int ROWW = BK + 4;          // 12 floats = 48B row (16B-aligned)

    __shared__ float AsH[2][BM][ROWW];
    __shared__ float AsL[2][BM][ROWW];
    __shared__ float BsH[2][BN][ROWW];
    __shared__ float BsL[2][BN][ROWW];

    const int tid = threadIdx.x;
    const int lane = tid & 31;
    const int warp = tid >> 5;
    const int wmIdx = warp >> 2;          // 0..3
    const int wnIdx = warp & 3;           // 0..3
    const int wm = wmIdx * 32;
    const int wn = wnIdx * 32;
    const int rowBase = blockIdx.y * BM;
    const int colBase = blockIdx.x * BN;

    constexpr uint32_t RS = ROWW * 4;     // 48B row stride
    const uint32_t aLane = ((lane & 7) + ((lane >> 3) & 1) * 8) * RS
                           + ((lane >> 4) & 1) * 16;
    const uint32_t bLane = ((lane & 7) + ((lane >> 4) & 1) * 8) * RS
                           + ((lane >> 3) & 1) * 16;

    const uint32_t aH = smemU32(&AsH[0][0][0]);
    const uint32_t aL = smemU32(&AsL[0][0][0]);
    const uint32_t bH = smemU32(&BsH[0][0][0]);
    const uint32_t bL = smemU32(&BsL[0][0][0]);
    constexpr uint32_t bufStride = BM * ROWW * 4;

    float acc[2][4][4];
    #pragma unroll
    for (int mi = 0; mi < 2; mi++)
        #pragma unroll
        for (int ni = 0; ni < 4; ni++)
            #pragma unroll
            for (int j = 0; j < 4; j++) acc[mi][ni][j] = 0.f;

    // staging: threads 0..255 stage A (row=tid>>1, col=(tid&1)*4);
    //          threads 256..511 stage B (n=t&127, kq=t>>7)
    float4 rA;
    float  rB[4];
    const bool isA = tid < 256;
    const int  sArow = tid >> 1;
    const int  sAcol = (tid & 1) << 2;
    const int  sBn  = (tid - 256) & 127;
    const int  sBkq = (tid - 256) >> 7;   // 0..1

    auto loadT = [&](int k0) {
        if (isA) {
            int gr = rowBase + sArow;
            rA = (gr < M)
                ? *reinterpret_cast<const float4*>(&A[(size_t)gr * K + k0 + sAcol])
                : make_float4(0.f, 0.f, 0.f, 0.f);
        } else {
            #pragma unroll
            for (int j = 0; j < 4; j++)
                rB[j] = B[(size_t)(k0 + sBkq * 4 + j) * N + colBase + sBn];
        }
    };
    auto storeT = [&](int buf) {
        if (isA) {
            float4 h, l;
            h.x = tf32r(rA.x); l.x = tf32r(rA.x - h.x);
            h.y = tf32r(rA.y); l.y = tf32r(rA.y - h.y);
            h.z = tf32r(rA.z); l.z = tf32r(rA.z - h.z);
            h.w = tf32r(rA.w); l.w = tf32r(rA.w - h.w);
            *reinterpret_cast<float4*>(&AsH[buf][sArow][sAcol]) = h;
            *reinterpret_cast<float4*>(&AsL[buf][sArow][sAcol]) = l;
        } else {
            float4 h, l;
            h.x = tf32r(rB[0]); l.x = tf32r(rB[0] - h.x);
            h.y = tf32r(rB[1]); l.y = tf32r(rB[1] - h.y);
            h.z = tf32r(rB[2]); l.z = tf32r(rB[2] - h.z);
            h.w = tf32r(rB[3]); l.w = tf32r(rB[3] - h.w);
            *reinterpret_cast<float4*>(&BsH[buf][sBn][sBkq * 4]) = h;
            *reinterpret_cast<float4*>(&BsL[buf][sBn][sBkq * 4]) = l;
        }
    };

    loadT(0);
    storeT(0);
    __syncthreads();

    const int KT = K / BK;
    int cur = 0;
    for (int kt = 0; kt < KT; kt++) {
        if (kt + 1 < KT) loadT((kt + 1) * BK);

        uint32_t afH[2][4], afL[2][4];
        uint32_t bfH[2][4], bfL[2][4];
        #pragma unroll
        for (int mi = 0; mi < 2; mi++) {
            uint32_t off = cur * bufStride + (wm + mi * 16) * RS + aLane;
            ldsm4(afH[mi], aH + off);
            ldsm4(afL[mi], aL + off);
        }
        #pragma unroll
        for (int p = 0; p < 2; p++) {
            uint32_t off = cur * bufStride + (wn + p * 16) * RS + bLane;
            ldsm4(bfH[p], bH + off);
            ldsm4(bfL[p], bL + off);
        }
        #pragma unroll
        for (int mi = 0; mi < 2; mi++)
            #pragma unroll
            for (int ni = 0; ni < 4; ni++) {
                const uint32_t* bh = &bfH[ni >> 1][(ni & 1) * 2];
                const uint32_t* bl = &bfL[ni >> 1][(ni & 1) * 2];
                mma_tf32(acc[mi][ni], afH[mi], bh);   // hi*hi
                mma_tf32(acc[mi][ni], afH[mi], bl);   // hi*lo
                mma_tf32(acc[mi][ni], afL[mi], bh);   // lo*hi
            }

        if (kt + 1 < KT) {
            int nb = cur ^ 1;
            storeT(nb);
            __syncthreads();
            cur = nb;
        }
    }

    // ---- epilogue: bias (+ReLU), store, per-column stats ----
    const int g = lane >> 2;       // row group 0..7
    const int cp = lane & 3;       // column pair 0..3
    float sA[4][2], qA[4][2];
    #pragma unroll
    for (int ni = 0; ni < 4; ni++) { sA[ni][0] = sA[ni][1] = qA[ni][0] = qA[ni][1] = 0.f; }

    #pragma unroll
    for (int mi = 0; mi < 2; mi++) {
        int r0 = rowBase + wm + mi * 16 + g;
        int r1 = r0 + 8;
        #pragma unroll
        for (int ni = 0; ni < 4; ni++) {
            int c = colBase + wn + ni * 8 + cp * 2;
            float bz0 = bias[c], bz1 = bias[c + 1];
            float v0 = acc[mi][ni][0] + bz0;
            float v1 = acc[mi][ni][1] + bz1;
            float v2 = acc[mi][ni][2] + bz0;
            float v3 = acc[mi][ni][3] + bz1;
            if (DO_RELU) {
                v0 = fmaxf(v0, 0.f); v1 = fmaxf(v1, 0.f);
                v2 = fmaxf(v2, 0.f); v3 = fmaxf(v3, 0.f);
            }
            if (r0 < M) {
                *reinterpret_cast<float2*>(&C[(size_t)r0 * N + c]) = make_float2(v0, v1);
                if (FUSE_STATS) {
                    sA[ni][0] += v0; sA[ni][1] += v1;
                    qA[ni][0] += v0 * v0; qA[ni][1] += v1 * v1;
                }
            }
            if (r1 < M) {
                *reinterpret_cast<float2*>(&C[(size_t)r1 * N + c]) = make_float2(v2, v3);
                if (FUSE_STATS) {
                    sA[ni][0] += v2; sA[ni][1] += v3;
                    qA[ni][0] += v2 * v2; qA[ni][1] += v3 * v3;
                }
            }
        }
    }

    if (FUSE_STATS) {
        __syncthreads();   // done with smem tiles; overlay stats scratch on AsH
        float* psum = &AsH[0][0][0];          // [4][BN]
        float* psq  = psum + 4 * BN;          // [4][BN]
        #pragma unroll
        for (int ni = 0; ni < 4; ni++) {
            float s0 = sA[ni][0], s1 = sA[ni][1];
            float q0 = qA[ni][0], q1 = qA[ni][1];
            #pragma unroll
            for (int off = 4; off <= 16; off <<= 1) {
                s0 += __shfl_xor_sync(0xffffffffu, s0, off);
                s1 += __shfl_xor_sync(0xffffffffu, s1, off);
                q0 += __shfl_xor_sync(0xffffffffu, q0, off);
                q1 += __shfl_xor_sync(0xffffffffu, q1, off);
            }
            if (lane < 4) {
                int c = wn + ni * 8 + lane * 2;
                psum[wmIdx * BN + c]     = s0;
                psum[wmIdx * BN + c + 1] = s1;
                psq [wmIdx * BN + c]     = q0;
                psq [wmIdx * BN + c + 1] = q1;
            }
        }
        __syncthreads();
        if (tid < 2 * BN) {
            int c = tid & (BN - 1);
            bool sq = tid >= BN;
            const float* base = sq ? psq : psum;
            float s = base[c] + base[BN + c] + base[2 * BN + c] + base[3 * BN + c];
            atomicAdd(&stats[(sq ? EMB_D : 0) + colBase + c], s);
        }
    }
}

// out = gamma*(h2-mu)*rsqrt(var+eps)+beta, optional ReLU
__global__ void bn_apply_kernel(const float* __restrict__ h2,
                                const float* __restrict__ stats,
                                const float* __restrict__ gamma,
                                const float* __restrict__ beta,
                                float* __restrict__ out, int relu)
{
    int i = blockIdx.x * blockDim.x + threadIdx.x;
    if (i >= N_NODES * EMB_D) return;
    int c = i & (EMB_D - 1);
    const float invN = 1.0f / (float)N_NODES;
    float mu = stats[c] * invN;
    float var = stats[EMB_D + c] * invN - mu * mu;
    float v = gamma[c] * (h2[i] - mu) * rsqrtf(var + BN_EPS) + beta[c];
    if (relu) v = fmaxf(v, 0.f);
    out[i] = v;
}

// ---------------- launch ----------------
extern "C" void kernel_launch(void* const* d_in, const int* in_sizes, int n_in,
                              void* d_out, int out_size)
{
    const int*   x    = (const int*)  d_in[0];
    const int*   ei   = (const int*)  d_in[1];
    const int*   ea   = (const int*)  d_in[2];
    const float* atom = (const float*)d_in[3];
    const float* chir = (const float*)d_in[4];
    const float* hyb  = (const float*)d_in[5];
    const float* e1   = (const float*)d_in[6];
    const float* e2   = (const float*)d_in[7];
    const float* W1   = (const float*)d_in[8];
    const float* b1   = (const float*)d_in[9];
    const float* W2   = (const float*)d_in[10];
    const float* b2   = (const float*)d_in[11];
    const float* gam  = (const float*)d_in[12];
    const float* bet  = (const float*)d_in[13];
    float* out = (float*)d_out;

    float *p_h, *p_agg, *p_t, *p_stats;
    cudaGetSymbolAddress((void**)&p_h, g_h);
    cudaGetSymbolAddress((void**)&p_agg, g_agg);
    cudaGetSymbolAddress((void**)&p_t, g_t);
    cudaGetSymbolAddress((void**)&p_stats, g_stats);

    {
        int total = N_NODES * (EMB_D / 4);
        embed_kernel<<<(total + 255) / 256, 256>>>(x, atom, chir, hyb, p_h);
    }

    const int scatterBlocks = (N_EDGES * 32 + 255) / 256;
    const int ewTotal = N_NODES * EMB_D;
    const int mTiles = (N_NODES + 127) / 128;

    for (int l = 0; l < NUM_LAYER; l++) {
        cudaMemsetAsync(p_agg, 0, (size_t)N_NODES * EMB_D * sizeof(float));
        cudaMemsetAsync(p_stats, 0, 2 * EMB_D * sizeof(float));

        scatter_kernel<<<scatterBlocks, 256>>>(
            p_h, ei, ea,
            e1 + (size_t)l * 6 * EMB_D,
            e2 + (size_t)l * 4 * EMB_D,
            p_agg);

        // GEMM1: t = relu(agg @ W1 + b1)   [N, 256]
        {
            dim3 grid(2, mTiles);
            tmma_gemm<1, 0><<<grid, 512>>>(
                p_agg, W1 + (size_t)l * EMB_D * 2 * EMB_D,
                b1 + (size_t)l * 2 * EMB_D, p_t,
                N_NODES, EMB_D, 2 * EMB_D, nullptr);
        }
        // GEMM2: h2 = t @ W2 + b2  [N, 128], fused BN stats
        {
            dim3 grid(1, mTiles);
            tmma_gemm<0, 1><<<grid, 512>>>(
                p_t, W2 + (size_t)l * 2 * EMB_D * EMB_D,
                b2 + (size_t)l * EMB_D, p_agg,
                N_NODES, 2 * EMB_D, EMB_D, p_stats);
        }

        float* dst = (l == NUM_LAYER - 1) ? out : p_h;
        int relu = (l == NUM_LAYER - 1) ? 0 : 1;
        bn_apply_kernel<<<(ewTotal + 255) / 256, 256>>>(
            p_agg, p_stats, gam + (size_t)l * EMB_D, bet + (size_t)l * EMB_D,
            dst, relu);
    }
}